// round 5
// baseline (speedup 1.0000x reference)
#include <cuda_runtime.h>
#include <float.h>
#include <math.h>

// Problem constants
#define NN   20000      // nodes
#define EE   320000     // edges (without self loops)
#define EPQ  340000     // edges + self loops
#define HHH  8          // GAT heads
#define GGG  64         // graphs
#define F1   256        // GAT out (H*32)
#define F2   512        // GCN1 out
#define F3   1024       // GCN2 / residual out

// ---------------------------------------------------------------------------
// Static scratch (no allocations allowed)
// ---------------------------------------------------------------------------
__device__ float g_h0  [NN * F1];     // x @ W_gat
__device__ float g_as  [NN * HHH];
__device__ float g_ad  [NN * HHH];
__device__ float g_emax[NN * HHH];
__device__ float g_esum[NN * HHH];
__device__ float g_ebuf[EPQ * HHH];   // per-edge attention scratch
__device__ float g_h1  [NN * F1];     // GAT output (post bias+relu)
__device__ float g_res [NN * F3];     // residual branch
__device__ float g_t   [NN * F3];     // GEMM output before aggregation (reused)
__device__ float g_a1  [NN * F2];     // GCN1 aggregate
__device__ float g_a2  [NN * F3];     // GCN2 aggregate
__device__ float g_dinv[NN];          // degree -> 1/sqrt(deg)
__device__ float g_pool[GGG * F3];    // per-graph max pool

// ---------------------------------------------------------------------------
// Helpers
// ---------------------------------------------------------------------------
__device__ __forceinline__ void atomicMaxFloat(float* addr, float val) {
    // Works for mixed-sign floats: int compare is monotone for non-negative
    // floats; unsigned compare is anti-monotone for negative floats.
    if (val >= 0.0f) atomicMax((int*)addr, __float_as_int(val));
    else             atomicMin((unsigned int*)addr, __float_as_uint(val));
}

// ---------------------------------------------------------------------------
// Init: identities for segment max/sum, zero accumulators
// ---------------------------------------------------------------------------
__global__ void k_init() {
    int i = blockIdx.x * blockDim.x + threadIdx.x;
    int stride = gridDim.x * blockDim.x;
    for (int j = i; j < NN * HHH; j += stride) { g_emax[j] = -FLT_MAX; g_esum[j] = 0.0f; }
    for (int j = i; j < NN * F1;  j += stride) g_h1[j] = 0.0f;
    for (int j = i; j < NN;       j += stride) g_dinv[j] = 0.0f;
    for (int j = i; j < GGG * F3; j += stride) g_pool[j] = -FLT_MAX;
}

// ---------------------------------------------------------------------------
// Generic tiled SGEMM: C[M,N] = A[M,K] @ B[K,N] (+ bias[N])
// BM=BN=64, BK=16, 256 threads, 4x4 microtile per thread.
// Requires: N % 64 == 0, K % 16 == 0 (all our shapes satisfy this).
// ---------------------------------------------------------------------------
#define BM 64
#define BN 64
#define BKK 16
__global__ __launch_bounds__(256) void sgemm_bias(
    const float* __restrict__ A, const float* __restrict__ B,
    float* __restrict__ C, const float* __restrict__ bias,
    int M, int N, int K)
{
    __shared__ float As[BKK][BM + 4];
    __shared__ float Bs[BKK][BN];

    int tid = threadIdx.x;
    int tx = tid & 15;        // 0..15 -> 4 cols each
    int ty = tid >> 4;        // 0..15 -> 4 rows each
    int rowBase = blockIdx.y * BM;
    int colBase = blockIdx.x * BN;

    int arow = tid >> 2;            // 0..63
    int acol = (tid & 3) << 2;      // 0,4,8,12
    int brow = tid >> 4;            // 0..15
    int bcol = (tid & 15) << 2;     // 0..60

    float acc[4][4] = {};

    for (int k0 = 0; k0 < K; k0 += BKK) {
        int gr = rowBase + arow;
        float4 av = make_float4(0.f, 0.f, 0.f, 0.f);
        if (gr < M) av = *(const float4*)(A + (size_t)gr * K + k0 + acol);
        As[acol + 0][arow] = av.x;
        As[acol + 1][arow] = av.y;
        As[acol + 2][arow] = av.z;
        As[acol + 3][arow] = av.w;

        float4 bv = *(const float4*)(B + (size_t)(k0 + brow) * N + colBase + bcol);
        *(float4*)&Bs[brow][bcol] = bv;
        __syncthreads();

        #pragma unroll
        for (int k = 0; k < BKK; ++k) {
            float am[4], bn[4];
            #pragma unroll
            for (int i = 0; i < 4; i++) am[i] = As[k][ty * 4 + i];
            #pragma unroll
            for (int j = 0; j < 4; j++) bn[j] = Bs[k][tx * 4 + j];
            #pragma unroll
            for (int i = 0; i < 4; i++)
                #pragma unroll
                for (int j = 0; j < 4; j++)
                    acc[i][j] = fmaf(am[i], bn[j], acc[i][j]);
        }
        __syncthreads();
    }

    #pragma unroll
    for (int i = 0; i < 4; i++) {
        int r = rowBase + ty * 4 + i;
        if (r < M) {
            #pragma unroll
            for (int j = 0; j < 4; j++) {
                int c = colBase + tx * 4 + j;
                float v = acc[i][j];
                if (bias) v += bias[c];
                C[(size_t)r * N + c] = v;
            }
        }
    }
}

// ---------------------------------------------------------------------------
// Attention dot products: a_s[n,h] = <h0[n,h*32:..], att_src[h]>, same for dst
// ---------------------------------------------------------------------------
__global__ void k_attn_dots(const float* __restrict__ att_s,
                            const float* __restrict__ att_d)
{
    int idx = blockIdx.x * blockDim.x + threadIdx.x;
    if (idx >= NN * HHH) return;
    int n = idx >> 3, h = idx & 7;
    const float* hp = g_h0 + (size_t)n * F1 + h * 32;
    const float* sa = att_s + h * 32;
    const float* da = att_d + h * 32;
    float s = 0.f, d = 0.f;
    #pragma unroll
    for (int c = 0; c < 32; ++c) {
        float hv = hp[c];
        s = fmaf(hv, sa[c], s);
        d = fmaf(hv, da[c], d);
    }
    g_as[idx] = s;
    g_ad[idx] = d;
}

// ---------------------------------------------------------------------------
// Edge pass 1: e = leaky_relu(a_s[src]+a_d[dst]); segment max; degree
// ---------------------------------------------------------------------------
__global__ void k_edge_pass1(const int* __restrict__ ei, const float* __restrict__ ew) {
    int stride = gridDim.x * blockDim.x;
    for (int idx = blockIdx.x * blockDim.x + threadIdx.x; idx < EPQ * HHH; idx += stride) {
        int e = idx >> 3, h = idx & 7;
        int src, dst; float w;
        if (e < EE) { src = ei[e]; dst = ei[EE + e]; w = ew[e]; }
        else        { src = dst = e - EE; w = 1.0f; }
        float v = g_as[src * HHH + h] + g_ad[dst * HHH + h];
        v = (v > 0.f) ? v : 0.2f * v;
        g_ebuf[idx] = v;
        atomicMaxFloat(&g_emax[dst * HHH + h], v);
        if (h == 0) atomicAdd(&g_dinv[dst], w);  // deg accumulation
    }
}

// Edge pass 2: ex = exp(e - max); segment sum
__global__ void k_edge_pass2(const int* __restrict__ ei) {
    int stride = gridDim.x * blockDim.x;
    for (int idx = blockIdx.x * blockDim.x + threadIdx.x; idx < EPQ * HHH; idx += stride) {
        int e = idx >> 3, h = idx & 7;
        int dst = (e < EE) ? ei[EE + e] : (e - EE);
        float ex = __expf(g_ebuf[idx] - g_emax[dst * HHH + h]);
        g_ebuf[idx] = ex;
        atomicAdd(&g_esum[dst * HHH + h], ex);
    }
}

// deg -> 1/sqrt(deg)
__global__ void k_dinv() {
    int n = blockIdx.x * blockDim.x + threadIdx.x;
    if (n >= NN) return;
    float d = g_dinv[n];
    g_dinv[n] = (d > 0.f) ? rsqrtf(fmaxf(d, 1e-12f)) : 0.0f;
}

// Edge pass 3: h1[dst] += h0[src] * alpha   (one block = one edge, 256 dims)
__global__ __launch_bounds__(256) void k_gat_scatter(const int* __restrict__ ei) {
    int e = blockIdx.x;
    int src, dst;
    if (e < EE) { src = ei[e]; dst = ei[EE + e]; }
    else        { src = dst = e - EE; }
    int j = threadIdx.x;            // 0..255
    int h = j >> 5;
    float alpha = g_ebuf[e * HHH + h] / g_esum[dst * HHH + h];
    atomicAdd(&g_h1[(size_t)dst * F1 + j], g_h0[(size_t)src * F1 + j] * alpha);
}

// GAT epilogue: h1 = relu(h1 + b_gat)
__global__ void k_gat_bias_relu(const float* __restrict__ b) {
    size_t i = (size_t)blockIdx.x * blockDim.x + threadIdx.x;
    if (i >= (size_t)NN * F1) return;
    int j = (int)(i & (F1 - 1));
    float v = g_h1[i] + b[j];
    g_h1[i] = v > 0.f ? v : 0.f;
}

// Fill aggregation buffer with bias (folds bias into segment sum)
__global__ void k_initbias(float* __restrict__ buf, const float* __restrict__ bias,
                           int total, int F) {
    int stride = gridDim.x * blockDim.x;
    for (int i = blockIdx.x * blockDim.x + threadIdx.x; i < total; i += stride)
        buf[i] = bias[i % F];
}

// GCN aggregation: agg[dst] += t[src] * (dinv[src]*w*dinv[dst]); blockDim = F/4
__global__ void k_gcn_scatter(const int* __restrict__ ei, const float* __restrict__ ew,
                              const float* __restrict__ t, float* __restrict__ agg, int F) {
    int e = blockIdx.x;
    int src, dst; float w;
    if (e < EE) { src = ei[e]; dst = ei[EE + e]; w = ew[e]; }
    else        { src = dst = e - EE; w = 1.0f; }
    float norm = g_dinv[src] * w * g_dinv[dst];
    int v = threadIdx.x;  // float4 index
    float4 x = *(const float4*)(t + (size_t)src * F + v * 4);
    float* o = agg + (size_t)dst * F + v * 4;
    atomicAdd(o + 0, x.x * norm);
    atomicAdd(o + 1, x.y * norm);
    atomicAdd(o + 2, x.z * norm);
    atomicAdd(o + 3, x.w * norm);
}

// BN + ReLU (in place)
__global__ void k_bn_relu(float* __restrict__ buf,
                          const float* __restrict__ g, const float* __restrict__ be,
                          const float* __restrict__ m, const float* __restrict__ v,
                          int total, int F) {
    int stride = gridDim.x * blockDim.x;
    for (int i = blockIdx.x * blockDim.x + threadIdx.x; i < total; i += stride) {
        int j = i % F;
        float x = buf[i];
        x = g[j] * (x - m[j]) * rsqrtf(v[j] + 1e-5f) + be[j];
        buf[i] = x > 0.f ? x : 0.f;
    }
}

// Final fuse: h = relu(bn2(a2)) + res; global max pool per graph
__global__ void k_final_pool(const float* __restrict__ g, const float* __restrict__ be,
                             const float* __restrict__ m, const float* __restrict__ v,
                             const int* __restrict__ batch) {
    int stride = gridDim.x * blockDim.x;
    for (int i = blockIdx.x * blockDim.x + threadIdx.x; i < NN * F3; i += stride) {
        int n = i >> 10;
        int j = i & (F3 - 1);
        float x = g_a2[i];
        x = g[j] * (x - m[j]) * rsqrtf(v[j] + 1e-5f) + be[j];
        x = (x > 0.f ? x : 0.f) + g_res[i];
        atomicMaxFloat(&g_pool[(size_t)batch[n] * F3 + j], x);
    }
}

// MLP head: one block per graph. z = relu(pool @ Wf1 + bf1); out = z @ Wf2 + bf2
__global__ __launch_bounds__(256) void k_head(
    const float* __restrict__ Wf1, const float* __restrict__ bf1,
    const float* __restrict__ Wf2, const float* __restrict__ bf2,
    float* __restrict__ out)
{
    __shared__ float sp[F3];
    __shared__ float sr0[256];
    __shared__ float sr1[256];
    int gb = blockIdx.x, tid = threadIdx.x;
    for (int i = tid; i < F3; i += 256) sp[i] = g_pool[(size_t)gb * F3 + i];
    __syncthreads();

    float acc = bf1[tid];
    #pragma unroll 4
    for (int k = 0; k < F3; ++k)
        acc = fmaf(sp[k], Wf1[(size_t)k * 256 + tid], acc);
    acc = acc > 0.f ? acc : 0.f;

    sr0[tid] = acc * Wf2[tid * 2 + 0];
    sr1[tid] = acc * Wf2[tid * 2 + 1];
    __syncthreads();
    for (int s = 128; s > 0; s >>= 1) {
        if (tid < s) { sr0[tid] += sr0[tid + s]; sr1[tid] += sr1[tid + s]; }
        __syncthreads();
    }
    if (tid == 0) {
        out[gb * 2 + 0] = sr0[0] + bf2[0];
        out[gb * 2 + 1] = sr1[0] + bf2[1];
    }
}

// ---------------------------------------------------------------------------
// Launch
// ---------------------------------------------------------------------------
extern "C" void kernel_launch(void* const* d_in, const int* in_sizes, int n_in,
                              void* d_out, int out_size)
{
    const float* x       = (const float*)d_in[0];
    const int*   ei      = (const int*)  d_in[1];
    const float* ew      = (const float*)d_in[2];
    const int*   batch   = (const int*)  d_in[3];
    const float* W_gat   = (const float*)d_in[4];
    const float* att_src = (const float*)d_in[5];
    const float* att_dst = (const float*)d_in[6];
    const float* b_gat   = (const float*)d_in[7];
    const float* W_res   = (const float*)d_in[8];
    const float* b_res   = (const float*)d_in[9];
    const float* W2      = (const float*)d_in[10];
    const float* b2      = (const float*)d_in[11];
    const float* g1      = (const float*)d_in[12];
    const float* be1     = (const float*)d_in[13];
    const float* m1      = (const float*)d_in[14];
    const float* v1      = (const float*)d_in[15];
    const float* W3      = (const float*)d_in[16];
    const float* b3      = (const float*)d_in[17];
    const float* g2      = (const float*)d_in[18];
    const float* be2     = (const float*)d_in[19];
    const float* m2      = (const float*)d_in[20];
    const float* v2      = (const float*)d_in[21];
    const float* Wf1     = (const float*)d_in[22];
    const float* bf1     = (const float*)d_in[23];
    const float* Wf2     = (const float*)d_in[24];
    const float* bf2     = (const float*)d_in[25];
    float* out = (float*)d_out;

    float *p_h0, *p_h1, *p_res, *p_t, *p_a1, *p_a2;
    cudaGetSymbolAddress((void**)&p_h0,  g_h0);
    cudaGetSymbolAddress((void**)&p_h1,  g_h1);
    cudaGetSymbolAddress((void**)&p_res, g_res);
    cudaGetSymbolAddress((void**)&p_t,   g_t);
    cudaGetSymbolAddress((void**)&p_a1,  g_a1);
    cudaGetSymbolAddress((void**)&p_a2,  g_a2);

    const int rowTiles = (NN + BM - 1) / BM;  // 313

    // init identities / zeros
    k_init<<<4096, 256>>>();

    // GAT: h0 = x @ W_gat   [20000,32]x[32,256]
    sgemm_bias<<<dim3(F1 / BN, rowTiles), 256>>>(x, W_gat, p_h0, nullptr, NN, F1, 32);

    // attention logits per node/head
    k_attn_dots<<<(NN * HHH + 255) / 256, 256>>>(att_src, att_dst);

    // edge softmax (3 passes) + degree
    k_edge_pass1<<<4096, 256>>>(ei, ew);
    k_edge_pass2<<<4096, 256>>>(ei);
    k_dinv<<<(NN + 255) / 256, 256>>>();
    k_gat_scatter<<<EPQ, 256>>>(ei);
    k_gat_bias_relu<<<(NN * F1 + 255) / 256, 256>>>(b_gat);

    // residual: res = h1 @ W_res + b_res   [20000,256]x[256,1024]
    sgemm_bias<<<dim3(F3 / BN, rowTiles), 256>>>(p_h1, W_res, p_res, b_res, NN, F3, F1);

    // GCN1: t = h1 @ W2 ; agg += t[src]*norm ; BN1 + relu
    sgemm_bias<<<dim3(F2 / BN, rowTiles), 256>>>(p_h1, W2, p_t, nullptr, NN, F2, F1);
    k_initbias<<<4096, 256>>>(p_a1, b2, NN * F2, F2);
    k_gcn_scatter<<<EPQ, F2 / 4>>>(ei, ew, p_t, p_a1, F2);
    k_bn_relu<<<4096, 256>>>(p_a1, g1, be1, m1, v1, NN * F2, F2);

    // GCN2: t = a1 @ W3 ; agg ; BN2 + relu + residual + pool (fused)
    sgemm_bias<<<dim3(F3 / BN, rowTiles), 256>>>(p_a1, W3, p_t, nullptr, NN, F3, F2);
    k_initbias<<<4096, 256>>>(p_a2, b3, NN * F3, F3);
    k_gcn_scatter<<<EPQ, F3 / 4>>>(ei, ew, p_t, p_a2, F3);
    k_final_pool<<<4096, 256>>>(g2, be2, m2, v2, batch);

    // MLP head
    k_head<<<GGG, 256>>>(Wf1, bf1, Wf2, bf2, out);
}

// round 7
// speedup vs baseline: 1.6417x; 1.6417x over previous
#include <cuda_runtime.h>
#include <float.h>
#include <math.h>

// Problem constants
#define NN   20000      // nodes
#define EE   320000     // edges (without self loops)
#define EPQ  340000     // edges + self loops
#define HHH  8          // GAT heads
#define GGG  64         // graphs
#define F1   256        // GAT out (H*32)
#define F2   512        // GCN1 out
#define F3   1024       // GCN2 / residual out
#define CAP  256        // smem edge cache per node (max degree ~50 in this data)

typedef unsigned long long u64;

// ---------------------------------------------------------------------------
// Static scratch (no allocations allowed)
// ---------------------------------------------------------------------------
__device__ float g_h0  [NN * F1];     // x @ W_gat
__device__ float g_as  [NN * HHH];
__device__ float g_ad  [NN * HHH];
__device__ float g_h1  [NN * F1];     // GAT output (post bias+relu)
__device__ float g_res [NN * F3];     // residual branch
__device__ float g_t   [NN * F3];     // GEMM output before aggregation (reused)
__device__ float g_a1  [NN * F2];     // GCN1 output (post BN+relu)
__device__ float g_dinv[NN];
__device__ float g_wdeg[NN];
__device__ float g_pool[GGG * F3];
// CSR
__device__ int   g_cnt [NN];
__device__ int   g_off [NN + 1];
__device__ int   g_cur [NN];
__device__ int   g_csrc[EPQ];
__device__ float g_cw  [EPQ];

// ---------------------------------------------------------------------------
// Helpers
// ---------------------------------------------------------------------------
__device__ __forceinline__ void atomicMaxFloat(float* addr, float val) {
    if (val >= 0.0f) atomicMax((int*)addr, __float_as_int(val));
    else             atomicMin((unsigned int*)addr, __float_as_uint(val));
}

__device__ __forceinline__ u64 dup2(float a) {
    u64 r;
    asm("mov.b64 %0, {%1, %1};" : "=l"(r) : "r"(__float_as_uint(a)));
    return r;
}
__device__ __forceinline__ u64 pack2(float lo, float hi) {
    u64 r;
    asm("mov.b64 %0, {%1, %2};" : "=l"(r) : "r"(__float_as_uint(lo)), "r"(__float_as_uint(hi)));
    return r;
}
__device__ __forceinline__ void unpack2(u64 v, float& lo, float& hi) {
    unsigned a, b;
    asm("mov.b64 {%0, %1}, %2;" : "=r"(a), "=r"(b) : "l"(v));
    lo = __uint_as_float(a); hi = __uint_as_float(b);
}
__device__ __forceinline__ void fma2(u64& d, u64 a, u64 b) {
    asm("fma.rn.f32x2 %0, %1, %2, %0;" : "+l"(d) : "l"(a), "l"(b));
}

// ---------------------------------------------------------------------------
// Init
// ---------------------------------------------------------------------------
__global__ void k_init() {
    int i = blockIdx.x * blockDim.x + threadIdx.x;
    int stride = gridDim.x * blockDim.x;
    for (int j = i; j < NN;       j += stride) { g_cnt[j] = 0; g_wdeg[j] = 0.0f; }
    for (int j = i; j < GGG * F3; j += stride) g_pool[j] = -FLT_MAX;
}

// ---------------------------------------------------------------------------
// CSR build
// ---------------------------------------------------------------------------
__global__ void k_count(const int* __restrict__ ei, const float* __restrict__ ew) {
    int e = blockIdx.x * blockDim.x + threadIdx.x;
    if (e >= EPQ) return;
    int dst; float w;
    if (e < EE) { dst = ei[EE + e]; w = ew[e]; }
    else        { dst = e - EE;     w = 1.0f; }
    atomicAdd(&g_cnt[dst], 1);
    atomicAdd(&g_wdeg[dst], w);
}

__global__ void k_scan() {   // 1 block, 1024 threads
    __shared__ int ssum[1024];
    __shared__ int carry;
    int tid = threadIdx.x;
    if (tid == 0) carry = 0;
    __syncthreads();
    for (int base = 0; base < NN; base += 1024) {
        int i = base + tid;
        int v = (i < NN) ? g_cnt[i] : 0;
        ssum[tid] = v;
        __syncthreads();
        for (int s = 1; s < 1024; s <<= 1) {
            int t = 0;
            if (tid >= s) t = ssum[tid - s];
            __syncthreads();
            if (tid >= s) ssum[tid] += t;
            __syncthreads();
        }
        int excl = ssum[tid] - v;
        if (i < NN) {
            int o = carry + excl;
            g_off[i] = o;
            g_cur[i] = o;
        }
        __syncthreads();
        if (tid == 1023) carry += ssum[1023];
        __syncthreads();
    }
    if (tid == 0) g_off[NN] = carry;
}

__global__ void k_dinv() {
    int n = blockIdx.x * blockDim.x + threadIdx.x;
    if (n >= NN) return;
    float d = g_wdeg[n];
    g_dinv[n] = (d > 0.f) ? rsqrtf(fmaxf(d, 1e-12f)) : 0.0f;
}

__global__ void k_fill(const int* __restrict__ ei, const float* __restrict__ ew) {
    int e = blockIdx.x * blockDim.x + threadIdx.x;
    if (e >= EPQ) return;
    int src, dst; float w;
    if (e < EE) { src = ei[e]; dst = ei[EE + e]; w = ew[e]; }
    else        { src = dst = e - EE; w = 1.0f; }
    int slot = atomicAdd(&g_cur[dst], 1);
    g_csrc[slot] = src;
    g_cw[slot]   = w;
}

// ---------------------------------------------------------------------------
// SGEMM with packed f32x2 FMA: C[M,N] = A[M,K] @ B[K,N] (+ bias[N])
// 128x128 tile, BK=16, 256 threads, 8x8 microtile (N paired into f32x2).
// Requires N % 128 == 0, K % 16 == 0.
// ---------------------------------------------------------------------------
#define GBM 128
#define GBN 128
#define GBK 16
__global__ __launch_bounds__(256, 2) void gemm_f32x2(
    const float* __restrict__ A, const float* __restrict__ B,
    float* __restrict__ C, const float* __restrict__ bias,
    int M, int N, int K)
{
    __shared__ float As[GBK][GBM + 4];   // [k][m], pitch 132 (16B aligned rows)
    __shared__ float Bs[GBK][GBN];       // [k][n]

    int tid = threadIdx.x;
    int tx = tid & 15;        // col group: cols tx*8 .. +7
    int ty = tid >> 4;        // row group: rows ty*8 .. +7
    int rowBase = blockIdx.y * GBM;
    int colBase = blockIdx.x * GBN;

    u64 acc[8][4];
    #pragma unroll
    for (int r = 0; r < 8; r++)
        #pragma unroll
        for (int j = 0; j < 4; j++) acc[r][j] = 0ull;

    float4 pa[2], pb[2];
    #pragma unroll
    for (int j = 0; j < 2; j++) {
        int f4 = tid + j * 256;
        int ar = f4 >> 2, ac4 = f4 & 3;
        int gr = rowBase + ar;
        pa[j] = make_float4(0.f, 0.f, 0.f, 0.f);
        if (gr < M) pa[j] = *(const float4*)(A + (size_t)gr * K + ac4 * 4);
        int br = f4 >> 5, bc4 = f4 & 31;
        pb[j] = *(const float4*)(B + (size_t)br * N + colBase + bc4 * 4);
    }

    for (int k0 = 0; k0 < K; k0 += GBK) {
        #pragma unroll
        for (int j = 0; j < 2; j++) {
            int f4 = tid + j * 256;
            int ar = f4 >> 2, ac4 = f4 & 3;
            As[ac4 * 4 + 0][ar] = pa[j].x;
            As[ac4 * 4 + 1][ar] = pa[j].y;
            As[ac4 * 4 + 2][ar] = pa[j].z;
            As[ac4 * 4 + 3][ar] = pa[j].w;
            int br = f4 >> 5, bc4 = f4 & 31;
            *(float4*)&Bs[br][bc4 * 4] = pb[j];
        }
        __syncthreads();

        if (k0 + GBK < K) {
            #pragma unroll
            for (int j = 0; j < 2; j++) {
                int f4 = tid + j * 256;
                int ar = f4 >> 2, ac4 = f4 & 3;
                int gr = rowBase + ar;
                pa[j] = make_float4(0.f, 0.f, 0.f, 0.f);
                if (gr < M) pa[j] = *(const float4*)(A + (size_t)gr * K + k0 + GBK + ac4 * 4);
                int br = f4 >> 5, bc4 = f4 & 31;
                pb[j] = *(const float4*)(B + (size_t)(k0 + GBK + br) * N + colBase + bc4 * 4);
            }
        }

        #pragma unroll
        for (int k = 0; k < GBK; k++) {
            float4 a0 = *(const float4*)&As[k][ty * 8];
            float4 a1 = *(const float4*)&As[k][ty * 8 + 4];
            float4 b0 = *(const float4*)&Bs[k][tx * 8];
            float4 b1 = *(const float4*)&Bs[k][tx * 8 + 4];
            u64 B0 = pack2(b0.x, b0.y), B1 = pack2(b0.z, b0.w);
            u64 B2 = pack2(b1.x, b1.y), B3 = pack2(b1.z, b1.w);
            float av[8] = {a0.x, a0.y, a0.z, a0.w, a1.x, a1.y, a1.z, a1.w};
            #pragma unroll
            for (int r = 0; r < 8; r++) {
                u64 Ar = dup2(av[r]);
                fma2(acc[r][0], Ar, B0);
                fma2(acc[r][1], Ar, B1);
                fma2(acc[r][2], Ar, B2);
                fma2(acc[r][3], Ar, B3);
            }
        }
        __syncthreads();
    }

    #pragma unroll
    for (int r = 0; r < 8; r++) {
        int row = rowBase + ty * 8 + r;
        if (row < M) {
            float* cp = C + (size_t)row * N + colBase + tx * 8;
            #pragma unroll
            for (int j = 0; j < 4; j++) {
                float lo, hi;
                unpack2(acc[r][j], lo, hi);
                if (bias) {
                    int c = colBase + tx * 8 + j * 2;
                    lo += bias[c];
                    hi += bias[c + 1];
                }
                *(float2*)(cp + j * 2) = make_float2(lo, hi);
            }
        }
    }
}

// ---------------------------------------------------------------------------
// Attention dot products
// ---------------------------------------------------------------------------
__global__ void k_attn_dots(const float* __restrict__ att_s,
                            const float* __restrict__ att_d)
{
    int idx = blockIdx.x * blockDim.x + threadIdx.x;
    if (idx >= NN * HHH) return;
    int n = idx >> 3, h = idx & 7;
    const float* hp = g_h0 + (size_t)n * F1 + h * 32;
    const float* sa = att_s + h * 32;
    const float* da = att_d + h * 32;
    float s = 0.f, d = 0.f;
    #pragma unroll
    for (int c = 0; c < 32; ++c) {
        float hv = hp[c];
        s = fmaf(hv, sa[c], s);
        d = fmaf(hv, da[c], d);
    }
    g_as[idx] = s;
    g_ad[idx] = d;
}

// ---------------------------------------------------------------------------
// Fused GAT: per-node softmax over incoming edges + feature gather + bias + relu
// One block (256 thr) per node. Warp w handles head w's softmax.
// ---------------------------------------------------------------------------
__global__ __launch_bounds__(256) void k_gat_gather(const float* __restrict__ b_gat) {
    __shared__ float s_alpha[CAP * HHH];   // 8KB
    __shared__ int   s_src[CAP];
    __shared__ float s_ad[HHH];
    __shared__ float s_ms[HHH], s_si[HHH];

    int n = blockIdx.x;
    int start = g_off[n];
    int deg = g_off[n + 1] - start;
    int tid = threadIdx.x;
    int w = tid >> 5, l = tid & 31;

    if (tid < HHH) s_ad[tid] = g_ad[n * HHH + tid];
    int degc = deg < CAP ? deg : CAP;
    for (int i = tid; i < degc; i += 256) s_src[i] = g_csrc[start + i];
    __syncthreads();

    // online softmax per head (warp w == head w)
    float m = -FLT_MAX, ssum = 0.f;
    float adh = s_ad[w];
    for (int i = l; i < deg; i += 32) {
        int src = (i < CAP) ? s_src[i] : g_csrc[start + i];
        float e = g_as[src * HHH + w] + adh;
        e = (e > 0.f) ? e : 0.2f * e;
        float mn = fmaxf(m, e);
        ssum = ssum * __expf(m - mn) + __expf(e - mn);
        m = mn;
        if (i < CAP) s_alpha[i * HHH + w] = e;   // stash raw e
    }
    #pragma unroll
    for (int off = 16; off > 0; off >>= 1) {
        float m2 = __shfl_xor_sync(0xffffffffu, m, off);
        float s2 = __shfl_xor_sync(0xffffffffu, ssum, off);
        float mn = fmaxf(m, m2);
        ssum = ssum * __expf(m - mn) + s2 * __expf(m2 - mn);
        m = mn;
    }
    float inv = 1.0f / ssum;
    // convert stashed e -> alpha
    for (int i = l; i < degc; i += 32)
        s_alpha[i * HHH + w] = __expf(s_alpha[i * HHH + w] - m) * inv;
    if (l == 0) { s_ms[w] = m; s_si[w] = inv; }
    __syncthreads();

    // gather features: thread tid owns feature j = tid; head h = j>>5
    int h = tid >> 5;
    float acc = 0.f;
    for (int i = 0; i < deg; i++) {
        int src; float alpha;
        if (i < CAP) { src = s_src[i]; alpha = s_alpha[i * HHH + h]; }
        else {
            src = g_csrc[start + i];
            float e = g_as[src * HHH + h] + s_ad[h];
            e = (e > 0.f) ? e : 0.2f * e;
            alpha = __expf(e - s_ms[h]) * s_si[h];
        }
        acc = fmaf(g_h0[(size_t)src * F1 + tid], alpha, acc);
    }
    float v = acc + b_gat[tid];
    g_h1[(size_t)n * F1 + tid] = v > 0.f ? v : 0.f;
}

// ---------------------------------------------------------------------------
// GCN gather, F=512 (float2/thread), epilogue: +b2, BN1, relu
// ---------------------------------------------------------------------------
__global__ __launch_bounds__(256) void k_gcn_gather_f2(
    const float* __restrict__ t,
    const float* __restrict__ b2,
    const float* __restrict__ g1, const float* __restrict__ be1,
    const float* __restrict__ m1, const float* __restrict__ v1)
{
    __shared__ int   s_src[CAP];
    __shared__ float s_nrm[CAP];
    int n = blockIdx.x;
    int start = g_off[n];
    int deg = g_off[n + 1] - start;
    int tid = threadIdx.x;
    float dn = g_dinv[n];
    int degc = deg < CAP ? deg : CAP;
    for (int i = tid; i < degc; i += 256) {
        int s = g_csrc[start + i];
        s_src[i] = s;
        s_nrm[i] = g_dinv[s] * g_cw[start + i] * dn;
    }
    __syncthreads();

    float2 acc = make_float2(0.f, 0.f);
    for (int i = 0; i < deg; i++) {
        int src; float nrm;
        if (i < CAP) { src = s_src[i]; nrm = s_nrm[i]; }
        else {
            src = g_csrc[start + i];
            nrm = g_dinv[src] * g_cw[start + i] * dn;
        }
        float2 x = *(const float2*)(t + (size_t)src * F2 + tid * 2);
        acc.x = fmaf(x.x, nrm, acc.x);
        acc.y = fmaf(x.y, nrm, acc.y);
    }
    int j = tid * 2;
    float sc0 = g1[j]     * rsqrtf(v1[j]     + 1e-5f);
    float sc1 = g1[j + 1] * rsqrtf(v1[j + 1] + 1e-5f);
    float y0 = sc0 * (acc.x + b2[j]     - m1[j])     + be1[j];
    float y1 = sc1 * (acc.y + b2[j + 1] - m1[j + 1]) + be1[j + 1];
    y0 = y0 > 0.f ? y0 : 0.f;
    y1 = y1 > 0.f ? y1 : 0.f;
    *(float2*)(g_a1 + (size_t)n * F2 + j) = make_float2(y0, y1);
}

// ---------------------------------------------------------------------------
// GCN gather, F=1024 (float4/thread), epilogue: +b3, BN2, relu, +res, max pool
// ---------------------------------------------------------------------------
__global__ __launch_bounds__(256) void k_gcn_gather_f3(
    const float* __restrict__ t,
    const float* __restrict__ b3,
    const float* __restrict__ g2, const float* __restrict__ be2,
    const float* __restrict__ m2, const float* __restrict__ v2,
    const int* __restrict__ batch)
{
    __shared__ int   s_src[CAP];
    __shared__ float s_nrm[CAP];
    int n = blockIdx.x;
    int start = g_off[n];
    int deg = g_off[n + 1] - start;
    int tid = threadIdx.x;
    float dn = g_dinv[n];
    int degc = deg < CAP ? deg : CAP;
    for (int i = tid; i < degc; i += 256) {
        int s = g_csrc[start + i];
        s_src[i] = s;
        s_nrm[i] = g_dinv[s] * g_cw[start + i] * dn;
    }
    __syncthreads();

    float4 acc = make_float4(0.f, 0.f, 0.f, 0.f);
    for (int i = 0; i < deg; i++) {
        int src; float nrm;
        if (i < CAP) { src = s_src[i]; nrm = s_nrm[i]; }
        else {
            src = g_csrc[start + i];
            nrm = g_dinv[src] * g_cw[start + i] * dn;
        }
        float4 x = *(const float4*)(t + (size_t)src * F3 + tid * 4);
        acc.x = fmaf(x.x, nrm, acc.x);
        acc.y = fmaf(x.y, nrm, acc.y);
        acc.z = fmaf(x.z, nrm, acc.z);
        acc.w = fmaf(x.w, nrm, acc.w);
    }
    int j = tid * 4;
    float4 rr = *(const float4*)(g_res + (size_t)n * F3 + j);
    float* pool = g_pool + (size_t)batch[n] * F3 + j;
    float a[4] = {acc.x, acc.y, acc.z, acc.w};
    float rs[4] = {rr.x, rr.y, rr.z, rr.w};
    #pragma unroll
    for (int c = 0; c < 4; c++) {
        float sc = g2[j + c] * rsqrtf(v2[j + c] + 1e-5f);
        float y = sc * (a[c] + b3[j + c] - m2[j + c]) + be2[j + c];
        y = (y > 0.f ? y : 0.f) + rs[c];
        atomicMaxFloat(pool + c, y);
    }
}

// ---------------------------------------------------------------------------
// MLP head
// ---------------------------------------------------------------------------
__global__ __launch_bounds__(256) void k_head(
    const float* __restrict__ Wf1, const float* __restrict__ bf1,
    const float* __restrict__ Wf2, const float* __restrict__ bf2,
    float* __restrict__ out)
{
    __shared__ float sp[F3];
    __shared__ float sr0[256];
    __shared__ float sr1[256];
    int gb = blockIdx.x, tid = threadIdx.x;
    for (int i = tid; i < F3; i += 256) sp[i] = g_pool[(size_t)gb * F3 + i];
    __syncthreads();

    float acc = bf1[tid];
    #pragma unroll 4
    for (int k = 0; k < F3; ++k)
        acc = fmaf(sp[k], Wf1[(size_t)k * 256 + tid], acc);
    acc = acc > 0.f ? acc : 0.f;

    sr0[tid] = acc * Wf2[tid * 2 + 0];
    sr1[tid] = acc * Wf2[tid * 2 + 1];
    __syncthreads();
    for (int s = 128; s > 0; s >>= 1) {
        if (tid < s) { sr0[tid] += sr0[tid + s]; sr1[tid] += sr1[tid + s]; }
        __syncthreads();
    }
    if (tid == 0) {
        out[gb * 2 + 0] = sr0[0] + bf2[0];
        out[gb * 2 + 1] = sr1[0] + bf2[1];
    }
}

// ---------------------------------------------------------------------------
// Launch
// ---------------------------------------------------------------------------
extern "C" void kernel_launch(void* const* d_in, const int* in_sizes, int n_in,
                              void* d_out, int out_size)
{
    const float* x       = (const float*)d_in[0];
    const int*   ei      = (const int*)  d_in[1];
    const float* ew      = (const float*)d_in[2];
    const int*   batch   = (const int*)  d_in[3];
    const float* W_gat   = (const float*)d_in[4];
    const float* att_src = (const float*)d_in[5];
    const float* att_dst = (const float*)d_in[6];
    const float* b_gat   = (const float*)d_in[7];
    const float* W_res   = (const float*)d_in[8];
    const float* b_res   = (const float*)d_in[9];
    const float* W2      = (const float*)d_in[10];
    const float* b2      = (const float*)d_in[11];
    const float* g1      = (const float*)d_in[12];
    const float* be1     = (const float*)d_in[13];
    const float* m1      = (const float*)d_in[14];
    const float* v1      = (const float*)d_in[15];
    const float* W3      = (const float*)d_in[16];
    const float* b3      = (const float*)d_in[17];
    const float* g2      = (const float*)d_in[18];
    const float* be2     = (const float*)d_in[19];
    const float* m2      = (const float*)d_in[20];
    const float* v2      = (const float*)d_in[21];
    const float* Wf1     = (const float*)d_in[22];
    const float* bf1     = (const float*)d_in[23];
    const float* Wf2     = (const float*)d_in[24];
    const float* bf2     = (const float*)d_in[25];
    float* out = (float*)d_out;

    float *p_h0, *p_h1, *p_res, *p_t, *p_a1;
    cudaGetSymbolAddress((void**)&p_h0,  g_h0);
    cudaGetSymbolAddress((void**)&p_h1,  g_h1);
    cudaGetSymbolAddress((void**)&p_res, g_res);
    cudaGetSymbolAddress((void**)&p_t,   g_t);
    cudaGetSymbolAddress((void**)&p_a1,  g_a1);

    const int rowTiles = (NN + GBM - 1) / GBM;  // 157
    const int egrid = (EPQ + 255) / 256;

    // CSR build (independent of GEMM results)
    k_init<<<512, 256>>>();
    k_count<<<egrid, 256>>>(ei, ew);
    k_scan<<<1, 1024>>>();
    k_dinv<<<(NN + 255) / 256, 256>>>();
    k_fill<<<egrid, 256>>>(ei, ew);

    // GAT: h0 = x @ W_gat   [20000,32]x[32,256]
    gemm_f32x2<<<dim3(F1 / GBN, rowTiles), 256>>>(x, W_gat, p_h0, nullptr, NN, F1, 32);
    k_attn_dots<<<(NN * HHH + 255) / 256, 256>>>(att_src, att_dst);
    k_gat_gather<<<NN, 256>>>(b_gat);

    // residual: res = h1 @ W_res + b_res   [20000,256]x[256,1024]
    gemm_f32x2<<<dim3(F3 / GBN, rowTiles), 256>>>(p_h1, W_res, p_res, b_res, NN, F3, F1);

    // GCN1: t = h1 @ W2 ; gather+BN1+relu
    gemm_f32x2<<<dim3(F2 / GBN, rowTiles), 256>>>(p_h1, W2, p_t, nullptr, NN, F2, F1);
    k_gcn_gather_f2<<<NN, 256>>>(p_t, b2, g1, be1, m1, v1);

    // GCN2: t = a1 @ W3 ; gather+BN2+relu+res+pool (fully fused)
    gemm_f32x2<<<dim3(F3 / GBN, rowTiles), 256>>>(p_a1, W3, p_t, nullptr, NN, F3, F2);
    k_gcn_gather_f3<<<NN, 256>>>(p_t, b3, g2, be2, m2, v2, batch);

    // MLP head
    k_head<<<GGG, 256>>>(Wf1, bf1, Wf2, bf2, out);
}

// round 8
// speedup vs baseline: 2.2567x; 1.3746x over previous
#include <cuda_runtime.h>
#include <cuda_bf16.h>
#include <float.h>
#include <math.h>

// Problem constants
#define NN   20000      // nodes
#define EE   320000     // edges (without self loops)
#define EPQ  340000     // edges + self loops
#define HHH  8          // GAT heads
#define GGG  64         // graphs
#define F1   256        // GAT out (H*32)
#define F2   512        // GCN1 out
#define F3   1024       // GCN2 / residual out
#define CAP  256        // smem edge cache per node

typedef unsigned long long u64;

// ---------------------------------------------------------------------------
// Static scratch (no allocations allowed)
// ---------------------------------------------------------------------------
__device__ float g_h0  [NN * F1];     // x @ W_gat
__device__ float g_as  [NN * HHH];
__device__ float g_ad  [NN * HHH];
__device__ float g_h1  [NN * F1];     // GAT output (post bias+relu)
__device__ float g_res [NN * F3];     // residual branch
__device__ float g_t   [NN * F3];     // GEMM output before aggregation (reused)
__device__ float g_a1  [NN * F2];     // GCN1 output (post BN+relu)
__device__ float g_dinv[NN];
__device__ float g_wdeg[NN];
__device__ float g_pool[GGG * F3];
// CSR
__device__ int   g_cnt [NN];
__device__ int   g_off [NN + 1];
__device__ int   g_cur [NN];
__device__ int   g_csrc[EPQ];
__device__ float g_cw  [EPQ];
// split-bf16 GEMM operands:  A' = [A_hi | A_lo | A_hi]  (M x 3K)
//                            B' = [B_hi ; B_hi ; B_lo]  (3K x N)
__device__ __nv_bfloat16 g_Ab[NN * 1536];      // max 3K = 1536
__device__ __nv_bfloat16 g_Bb[1536 * 1024];

// ---------------------------------------------------------------------------
// Helpers
// ---------------------------------------------------------------------------
__device__ __forceinline__ void atomicMaxFloat(float* addr, float val) {
    if (val >= 0.0f) atomicMax((int*)addr, __float_as_int(val));
    else             atomicMin((unsigned int*)addr, __float_as_uint(val));
}

__device__ __forceinline__ void ldsm4(unsigned& r0, unsigned& r1, unsigned& r2, unsigned& r3,
                                      unsigned a) {
    asm volatile("ldmatrix.sync.aligned.m8n8.x4.shared.b16 {%0,%1,%2,%3},[%4];"
                 : "=r"(r0), "=r"(r1), "=r"(r2), "=r"(r3) : "r"(a));
}
__device__ __forceinline__ void ldsm4t(unsigned& r0, unsigned& r1, unsigned& r2, unsigned& r3,
                                       unsigned a) {
    asm volatile("ldmatrix.sync.aligned.m8n8.x4.trans.shared.b16 {%0,%1,%2,%3},[%4];"
                 : "=r"(r0), "=r"(r1), "=r"(r2), "=r"(r3) : "r"(a));
}
__device__ __forceinline__ void mma16816(float* c, const unsigned* a, unsigned b0, unsigned b1) {
    asm volatile(
        "mma.sync.aligned.m16n8k16.row.col.f32.bf16.bf16.f32 "
        "{%0,%1,%2,%3}, {%4,%5,%6,%7}, {%8,%9}, {%0,%1,%2,%3};"
        : "+f"(c[0]), "+f"(c[1]), "+f"(c[2]), "+f"(c[3])
        : "r"(a[0]), "r"(a[1]), "r"(a[2]), "r"(a[3]), "r"(b0), "r"(b1));
}

// ---------------------------------------------------------------------------
// Init
// ---------------------------------------------------------------------------
__global__ void k_init() {
    int i = blockIdx.x * blockDim.x + threadIdx.x;
    int stride = gridDim.x * blockDim.x;
    for (int j = i; j < NN;       j += stride) { g_cnt[j] = 0; g_wdeg[j] = 0.0f; }
    for (int j = i; j < GGG * F3; j += stride) g_pool[j] = -FLT_MAX;
}

// ---------------------------------------------------------------------------
// CSR build
// ---------------------------------------------------------------------------
__global__ void k_count(const int* __restrict__ ei, const float* __restrict__ ew) {
    int e = blockIdx.x * blockDim.x + threadIdx.x;
    if (e >= EPQ) return;
    int dst; float w;
    if (e < EE) { dst = ei[EE + e]; w = ew[e]; }
    else        { dst = e - EE;     w = 1.0f; }
    atomicAdd(&g_cnt[dst], 1);
    atomicAdd(&g_wdeg[dst], w);
}

__global__ void k_scan() {   // 1 block, 1024 threads
    __shared__ int ssum[1024];
    __shared__ int carry;
    int tid = threadIdx.x;
    if (tid == 0) carry = 0;
    __syncthreads();
    for (int base = 0; base < NN; base += 1024) {
        int i = base + tid;
        int v = (i < NN) ? g_cnt[i] : 0;
        ssum[tid] = v;
        __syncthreads();
        for (int s = 1; s < 1024; s <<= 1) {
            int t = 0;
            if (tid >= s) t = ssum[tid - s];
            __syncthreads();
            if (tid >= s) ssum[tid] += t;
            __syncthreads();
        }
        int excl = ssum[tid] - v;
        if (i < NN) {
            int o = carry + excl;
            g_off[i] = o;
            g_cur[i] = o;
        }
        __syncthreads();
        if (tid == 1023) carry += ssum[1023];
        __syncthreads();
    }
    if (tid == 0) g_off[NN] = carry;
}

__global__ void k_dinv() {
    int n = blockIdx.x * blockDim.x + threadIdx.x;
    if (n >= NN) return;
    float d = g_wdeg[n];
    g_dinv[n] = (d > 0.f) ? rsqrtf(fmaxf(d, 1e-12f)) : 0.0f;
}

__global__ void k_fill(const int* __restrict__ ei, const float* __restrict__ ew) {
    int e = blockIdx.x * blockDim.x + threadIdx.x;
    if (e >= EPQ) return;
    int src, dst; float w;
    if (e < EE) { src = ei[e]; dst = ei[EE + e]; w = ew[e]; }
    else        { src = dst = e - EE; w = 1.0f; }
    int slot = atomicAdd(&g_cur[dst], 1);
    g_csrc[slot] = src;
    g_cw[slot]   = w;
}

// ---------------------------------------------------------------------------
// Split fp32 -> bf16 hi/lo operand builders
// A' [M, 3K] = [hi | lo | hi]
// ---------------------------------------------------------------------------
__global__ void k_splitA(const float* __restrict__ src, __nv_bfloat16* __restrict__ dst,
                         int M, int K) {
    int stride = gridDim.x * blockDim.x;
    int total = M * K;
    for (int i = blockIdx.x * blockDim.x + threadIdx.x; i < total; i += stride) {
        int row = i / K, k = i - row * K;
        float x = src[i];
        __nv_bfloat16 hi = __float2bfloat16(x);
        __nv_bfloat16 lo = __float2bfloat16(x - __bfloat162float(hi));
        size_t rb = (size_t)row * 3 * K;
        dst[rb + k]         = hi;
        dst[rb + K + k]     = lo;
        dst[rb + 2 * K + k] = hi;
    }
}
// B' [3K, N] = [hi ; hi ; lo]
__global__ void k_splitB(const float* __restrict__ src, __nv_bfloat16* __restrict__ dst,
                         int K, int N) {
    int stride = gridDim.x * blockDim.x;
    int total = K * N;
    for (int i = blockIdx.x * blockDim.x + threadIdx.x; i < total; i += stride) {
        int k = i / N, n = i - k * N;
        float x = src[i];
        __nv_bfloat16 hi = __float2bfloat16(x);
        __nv_bfloat16 lo = __float2bfloat16(x - __bfloat162float(hi));
        dst[(size_t)k * N + n]           = hi;
        dst[(size_t)(K + k) * N + n]     = hi;
        dst[(size_t)(2 * K + k) * N + n] = lo;
    }
}

// ---------------------------------------------------------------------------
// bf16 tensor-core GEMM: C[M,N] (fp32) = A'[M,Kp] @ B'[Kp,N] (+ bias[N])
// CTA tile 128x128, BK=32, 256 threads (8 warps, warp tile 32x64).
// mma.sync.m16n8k16 bf16 -> f32, ldmatrix with conflict-free pitches.
// Requires N % 128 == 0, Kp % 32 == 0.
// ---------------------------------------------------------------------------
#define APITCH 40     // bf16 elems per A smem row (bank step 20 -> conflict free)
#define BPITCH 136    // bf16 elems per B smem row (bank step 4  -> conflict free)
#define ABUFB  (128 * APITCH * 2)   // bytes per A buffer
#define BBUFB  (32 * BPITCH * 2)    // bytes per B buffer

__global__ __launch_bounds__(256) void gemm_bf16s(
    const __nv_bfloat16* __restrict__ Ab, const __nv_bfloat16* __restrict__ Bb,
    float* __restrict__ C, const float* __restrict__ bias,
    int M, int N, int Kp)
{
    __shared__ __align__(16) __nv_bfloat16 As[2][128 * APITCH];
    __shared__ __align__(16) __nv_bfloat16 Bs[2][32 * BPITCH];

    int tid = threadIdx.x;
    int wid = tid >> 5, lane = tid & 31;
    int wm = (wid >> 1) * 32;        // warp m offset within tile (4 rows of warps)
    int wn = (wid & 1) * 64;         // warp n offset (2 cols of warps)
    int g = lane >> 2, qp = lane & 3;
    int rowBase = blockIdx.y * 128;
    int colBase = blockIdx.x * 128;

    unsigned aBase = (unsigned)__cvta_generic_to_shared(&As[0][0]);
    unsigned bBase = (unsigned)__cvta_generic_to_shared(&Bs[0][0]);

    float cf[2][8][4];
    #pragma unroll
    for (int mf = 0; mf < 2; mf++)
        #pragma unroll
        for (int nf = 0; nf < 8; nf++)
            #pragma unroll
            for (int q = 0; q < 4; q++) cf[mf][nf][q] = 0.f;

    const uint4 zero4 = make_uint4(0u, 0u, 0u, 0u);

    // per-thread load coordinates (2 x 16B chunks each for A and B)
    int ar0 = tid >> 2,              akc0 = tid & 3;
    int ar1 = (tid + 256) >> 2,      akc1 = tid & 3;       // +256: same kc, row+64
    int br0 = tid >> 4,              bnc0 = tid & 15;
    int br1 = (tid + 256) >> 4,      bnc1 = tid & 15;      // row+16

    uint4 pa0, pa1, pb0, pb1;
    {
        int r = rowBase + ar0;
        pa0 = (r < M) ? *(const uint4*)(Ab + (size_t)r * Kp + akc0 * 8) : zero4;
        r = rowBase + ar1;
        pa1 = (r < M) ? *(const uint4*)(Ab + (size_t)r * Kp + akc1 * 8) : zero4;
        pb0 = *(const uint4*)(Bb + (size_t)br0 * N + colBase + bnc0 * 8);
        pb1 = *(const uint4*)(Bb + (size_t)br1 * N + colBase + bnc1 * 8);
    }

    int KT = Kp >> 5;
    int buf = 0;
    // store tile 0
    *(uint4*)(&As[0][ar0 * APITCH + akc0 * 8]) = pa0;
    *(uint4*)(&As[0][ar1 * APITCH + akc1 * 8]) = pa1;
    *(uint4*)(&Bs[0][br0 * BPITCH + bnc0 * 8]) = pb0;
    *(uint4*)(&Bs[0][br1 * BPITCH + bnc1 * 8]) = pb1;
    __syncthreads();

    for (int kt = 0; kt < KT; kt++) {
        // prefetch next tile into registers
        if (kt + 1 < KT) {
            int k0 = (kt + 1) << 5;
            int r = rowBase + ar0;
            pa0 = (r < M) ? *(const uint4*)(Ab + (size_t)r * Kp + k0 + akc0 * 8) : zero4;
            r = rowBase + ar1;
            pa1 = (r < M) ? *(const uint4*)(Ab + (size_t)r * Kp + k0 + akc1 * 8) : zero4;
            pb0 = *(const uint4*)(Bb + (size_t)(k0 + br0) * N + colBase + bnc0 * 8);
            pb1 = *(const uint4*)(Bb + (size_t)(k0 + br1) * N + colBase + bnc1 * 8);
        }

        // compute on buf
        unsigned aOff = aBase + buf * ABUFB;
        unsigned bOff = bBase + buf * BBUFB;
        #pragma unroll
        for (int ks = 0; ks < 32; ks += 16) {
            unsigned af[2][4];
            #pragma unroll
            for (int mf = 0; mf < 2; mf++) {
                unsigned addr = aOff +
                    (((wm + mf * 16 + (lane & 15)) * APITCH) + ks + ((lane >> 4) << 3)) * 2;
                ldsm4(af[mf][0], af[mf][1], af[mf][2], af[mf][3], addr);
            }
            #pragma unroll
            for (int p = 0; p < 4; p++) {
                unsigned bfr[4];
                unsigned addr = bOff +
                    (((ks + (lane & 15)) * BPITCH) + wn + p * 16 + ((lane >> 4) << 3)) * 2;
                ldsm4t(bfr[0], bfr[1], bfr[2], bfr[3], addr);
                #pragma unroll
                for (int mf = 0; mf < 2; mf++) {
                    mma16816(cf[mf][2 * p],     af[mf], bfr[0], bfr[1]);
                    mma16816(cf[mf][2 * p + 1], af[mf], bfr[2], bfr[3]);
                }
            }
        }

        if (kt + 1 < KT) {
            int nb = buf ^ 1;
            *(uint4*)(&As[nb][ar0 * APITCH + akc0 * 8]) = pa0;
            *(uint4*)(&As[nb][ar1 * APITCH + akc1 * 8]) = pa1;
            *(uint4*)(&Bs[nb][br0 * BPITCH + bnc0 * 8]) = pb0;
            *(uint4*)(&Bs[nb][br1 * BPITCH + bnc1 * 8]) = pb1;
            __syncthreads();
            buf = nb;
        }
    }

    // epilogue
    #pragma unroll
    for (int mf = 0; mf < 2; mf++) {
        #pragma unroll
        for (int nf = 0; nf < 8; nf++) {
            int col = colBase + wn + nf * 8 + qp * 2;
            float b0 = 0.f, b1 = 0.f;
            if (bias) { b0 = bias[col]; b1 = bias[col + 1]; }
            int row0 = rowBase + wm + mf * 16 + g;
            if (row0 < M)
                *(float2*)(C + (size_t)row0 * N + col) =
                    make_float2(cf[mf][nf][0] + b0, cf[mf][nf][1] + b1);
            int row1 = row0 + 8;
            if (row1 < M)
                *(float2*)(C + (size_t)row1 * N + col) =
                    make_float2(cf[mf][nf][2] + b0, cf[mf][nf][3] + b1);
        }
    }
}

// ---------------------------------------------------------------------------
// Attention dot products
// ---------------------------------------------------------------------------
__global__ void k_attn_dots(const float* __restrict__ att_s,
                            const float* __restrict__ att_d)
{
    int idx = blockIdx.x * blockDim.x + threadIdx.x;
    if (idx >= NN * HHH) return;
    int n = idx >> 3, h = idx & 7;
    const float* hp = g_h0 + (size_t)n * F1 + h * 32;
    const float* sa = att_s + h * 32;
    const float* da = att_d + h * 32;
    float s = 0.f, d = 0.f;
    #pragma unroll
    for (int c = 0; c < 32; ++c) {
        float hv = hp[c];
        s = fmaf(hv, sa[c], s);
        d = fmaf(hv, da[c], d);
    }
    g_as[idx] = s;
    g_ad[idx] = d;
}

// ---------------------------------------------------------------------------
// Fused GAT: per-node softmax over incoming edges + feature gather + bias + relu
// ---------------------------------------------------------------------------
__global__ __launch_bounds__(256) void k_gat_gather(const float* __restrict__ b_gat) {
    __shared__ float s_alpha[CAP * HHH];
    __shared__ int   s_src[CAP];
    __shared__ float s_ad[HHH];
    __shared__ float s_ms[HHH], s_si[HHH];

    int n = blockIdx.x;
    int start = g_off[n];
    int deg = g_off[n + 1] - start;
    int tid = threadIdx.x;
    int w = tid >> 5, l = tid & 31;

    if (tid < HHH) s_ad[tid] = g_ad[n * HHH + tid];
    int degc = deg < CAP ? deg : CAP;
    for (int i = tid; i < degc; i += 256) s_src[i] = g_csrc[start + i];
    __syncthreads();

    float m = -FLT_MAX, ssum = 0.f;
    float adh = s_ad[w];
    for (int i = l; i < deg; i += 32) {
        int src = (i < CAP) ? s_src[i] : g_csrc[start + i];
        float e = g_as[src * HHH + w] + adh;
        e = (e > 0.f) ? e : 0.2f * e;
        float mn = fmaxf(m, e);
        ssum = ssum * __expf(m - mn) + __expf(e - mn);
        m = mn;
        if (i < CAP) s_alpha[i * HHH + w] = e;
    }
    #pragma unroll
    for (int off = 16; off > 0; off >>= 1) {
        float m2 = __shfl_xor_sync(0xffffffffu, m, off);
        float s2 = __shfl_xor_sync(0xffffffffu, ssum, off);
        float mn = fmaxf(m, m2);
        ssum = ssum * __expf(m - mn) + s2 * __expf(m2 - mn);
        m = mn;
    }
    float inv = 1.0f / ssum;
    for (int i = l; i < degc; i += 32)
        s_alpha[i * HHH + w] = __expf(s_alpha[i * HHH + w] - m) * inv;
    if (l == 0) { s_ms[w] = m; s_si[w] = inv; }
    __syncthreads();

    int h = tid >> 5;
    float acc = 0.f;
    for (int i = 0; i < deg; i++) {
        int src; float alpha;
        if (i < CAP) { src = s_src[i]; alpha = s_alpha[i * HHH + h]; }
        else {
            src = g_csrc[start + i];
            float e = g_as[src * HHH + h] + s_ad[h];
            e = (e > 0.f) ? e : 0.2f * e;
            alpha = __expf(e - s_ms[h]) * s_si[h];
        }
        acc = fmaf(g_h0[(size_t)src * F1 + tid], alpha, acc);
    }
    float v = acc + b_gat[tid];
    g_h1[(size_t)n * F1 + tid] = v > 0.f ? v : 0.f;
}

// ---------------------------------------------------------------------------
// GCN gather, F=512 (float2/thread), epilogue: +b2, BN1, relu
// ---------------------------------------------------------------------------
__global__ __launch_bounds__(256) void k_gcn_gather_f2(
    const float* __restrict__ t,
    const float* __restrict__ b2,
    const float* __restrict__ g1, const float* __restrict__ be1,
    const float* __restrict__ m1, const float* __restrict__ v1)
{
    __shared__ int   s_src[CAP];
    __shared__ float s_nrm[CAP];
    int n = blockIdx.x;
    int start = g_off[n];
    int deg = g_off[n + 1] - start;
    int tid = threadIdx.x;
    float dn = g_dinv[n];
    int degc = deg < CAP ? deg : CAP;
    for (int i = tid; i < degc; i += 256) {
        int s = g_csrc[start + i];
        s_src[i] = s;
        s_nrm[i] = g_dinv[s] * g_cw[start + i] * dn;
    }
    __syncthreads();

    float2 acc = make_float2(0.f, 0.f);
    for (int i = 0; i < deg; i++) {
        int src; float nrm;
        if (i < CAP) { src = s_src[i]; nrm = s_nrm[i]; }
        else {
            src = g_csrc[start + i];
            nrm = g_dinv[src] * g_cw[start + i] * dn;
        }
        float2 x = *(const float2*)(t + (size_t)src * F2 + tid * 2);
        acc.x = fmaf(x.x, nrm, acc.x);
        acc.y = fmaf(x.y, nrm, acc.y);
    }
    int j = tid * 2;
    float sc0 = g1[j]     * rsqrtf(v1[j]     + 1e-5f);
    float sc1 = g1[j + 1] * rsqrtf(v1[j + 1] + 1e-5f);
    float y0 = sc0 * (acc.x + b2[j]     - m1[j])     + be1[j];
    float y1 = sc1 * (acc.y + b2[j + 1] - m1[j + 1]) + be1[j + 1];
    y0 = y0 > 0.f ? y0 : 0.f;
    y1 = y1 > 0.f ? y1 : 0.f;
    *(float2*)(g_a1 + (size_t)n * F2 + j) = make_float2(y0, y1);
}

// ---------------------------------------------------------------------------
// GCN gather, F=1024 (float4/thread), epilogue: +b3, BN2, relu, +res, max pool
// ---------------------------------------------------------------------------
__global__ __launch_bounds__(256) void k_gcn_gather_f3(
    const float* __restrict__ t,
    const float* __restrict__ b3,
    const float* __restrict__ g2, const float* __restrict__ be2,
    const float* __restrict__ m2, const float* __restrict__ v2,
    const int* __restrict__ batch)
{
    __shared__ int   s_src[CAP];
    __shared__ float s_nrm[CAP];
    int n = blockIdx.x;
    int start = g_off[n];
    int deg = g_off[n + 1] - start;
    int tid = threadIdx.x;
    float dn = g_dinv[n];
    int degc = deg < CAP ? deg : CAP;
    for (int i = tid; i < degc; i += 256) {
        int s = g_csrc[start + i];
        s_src[i] = s;
        s_nrm[i] = g_dinv[s] * g_cw[start + i] * dn;
    }
    __syncthreads();

    float4 acc = make_float4(0.f, 0.f, 0.f, 0.f);
    for (int i = 0; i < deg; i++) {
        int src; float nrm;
        if (i < CAP) { src = s_src[i]; nrm = s_nrm[i]; }
        else {
            src = g_csrc[start + i];
            nrm = g_dinv[src] * g_cw[start + i] * dn;
        }
        float4 x = *(const float4*)(t + (size_t)src * F3 + tid * 4);
        acc.x = fmaf(x.x, nrm, acc.x);
        acc.y = fmaf(x.y, nrm, acc.y);
        acc.z = fmaf(x.z, nrm, acc.z);
        acc.w = fmaf(x.w, nrm, acc.w);
    }
    int j = tid * 4;
    float4 rr = *(const float4*)(g_res + (size_t)n * F3 + j);
    float* pool = g_pool + (size_t)batch[n] * F3 + j;
    float a[4] = {acc.x, acc.y, acc.z, acc.w};
    float rs[4] = {rr.x, rr.y, rr.z, rr.w};
    #pragma unroll
    for (int c = 0; c < 4; c++) {
        float sc = g2[j + c] * rsqrtf(v2[j + c] + 1e-5f);
        float y = sc * (a[c] + b3[j + c] - m2[j + c]) + be2[j + c];
        y = (y > 0.f ? y : 0.f) + rs[c];
        atomicMaxFloat(pool + c, y);
    }
}

// ---------------------------------------------------------------------------
// MLP head
// ---------------------------------------------------------------------------
__global__ __launch_bounds__(256) void k_head(
    const float* __restrict__ Wf1, const float* __restrict__ bf1,
    const float* __restrict__ Wf2, const float* __restrict__ bf2,
    float* __restrict__ out)
{
    __shared__ float sp[F3];
    __shared__ float sr0[256];
    __shared__ float sr1[256];
    int gb = blockIdx.x, tid = threadIdx.x;
    for (int i = tid; i < F3; i += 256) sp[i] = g_pool[(size_t)gb * F3 + i];
    __syncthreads();

    float acc = bf1[tid];
    #pragma unroll 4
    for (int k = 0; k < F3; ++k)
        acc = fmaf(sp[k], Wf1[(size_t)k * 256 + tid], acc);
    acc = acc > 0.f ? acc : 0.f;

    sr0[tid] = acc * Wf2[tid * 2 + 0];
    sr1[tid] = acc * Wf2[tid * 2 + 1];
    __syncthreads();
    for (int s = 128; s > 0; s >>= 1) {
        if (tid < s) { sr0[tid] += sr0[tid + s]; sr1[tid] += sr1[tid + s]; }
        __syncthreads();
    }
    if (tid == 0) {
        out[gb * 2 + 0] = sr0[0] + bf2[0];
        out[gb * 2 + 1] = sr1[0] + bf2[1];
    }
}

// ---------------------------------------------------------------------------
// Launch
// ---------------------------------------------------------------------------
extern "C" void kernel_launch(void* const* d_in, const int* in_sizes, int n_in,
                              void* d_out, int out_size)
{
    const float* x       = (const float*)d_in[0];
    const int*   ei      = (const int*)  d_in[1];
    const float* ew      = (const float*)d_in[2];
    const int*   batch   = (const int*)  d_in[3];
    const float* W_gat   = (const float*)d_in[4];
    const float* att_src = (const float*)d_in[5];
    const float* att_dst = (const float*)d_in[6];
    const float* b_gat   = (const float*)d_in[7];
    const float* W_res   = (const float*)d_in[8];
    const float* b_res   = (const float*)d_in[9];
    const float* W2      = (const float*)d_in[10];
    const float* b2      = (const float*)d_in[11];
    const float* g1      = (const float*)d_in[12];
    const float* be1     = (const float*)d_in[13];
    const float* m1      = (const float*)d_in[14];
    const float* v1      = (const float*)d_in[15];
    const float* W3      = (const float*)d_in[16];
    const float* b3      = (const float*)d_in[17];
    const float* g2      = (const float*)d_in[18];
    const float* be2     = (const float*)d_in[19];
    const float* m2      = (const float*)d_in[20];
    const float* v2      = (const float*)d_in[21];
    const float* Wf1     = (const float*)d_in[22];
    const float* bf1     = (const float*)d_in[23];
    const float* Wf2     = (const float*)d_in[24];
    const float* bf2     = (const float*)d_in[25];
    float* out = (float*)d_out;

    float *p_h0, *p_h1, *p_res, *p_t, *p_a1;
    __nv_bfloat16 *p_Ab, *p_Bb;
    cudaGetSymbolAddress((void**)&p_h0,  g_h0);
    cudaGetSymbolAddress((void**)&p_h1,  g_h1);
    cudaGetSymbolAddress((void**)&p_res, g_res);
    cudaGetSymbolAddress((void**)&p_t,   g_t);
    cudaGetSymbolAddress((void**)&p_a1,  g_a1);
    cudaGetSymbolAddress((void**)&p_Ab,  g_Ab);
    cudaGetSymbolAddress((void**)&p_Bb,  g_Bb);

    const int rowTiles = (NN + 127) / 128;  // 157
    const int egrid = (EPQ + 255) / 256;

    // CSR build
    k_init<<<512, 256>>>();
    k_count<<<egrid, 256>>>(ei, ew);
    k_scan<<<1, 1024>>>();
    k_dinv<<<(NN + 255) / 256, 256>>>();
    k_fill<<<egrid, 256>>>(ei, ew);

    // GAT: h0 = x @ W_gat   [20000,32]x[32,256]  (split-bf16, Kp=96)
    k_splitA<<<2048, 256>>>(x, p_Ab, NN, 32);
    k_splitB<<<64, 256>>>(W_gat, p_Bb, 32, F1);
    gemm_bf16s<<<dim3(F1 / 128, rowTiles), 256>>>(p_Ab, p_Bb, p_h0, nullptr, NN, F1, 96);
    k_attn_dots<<<(NN * HHH + 255) / 256, 256>>>(att_src, att_dst);
    k_gat_gather<<<NN, 256>>>(b_gat);

    // h1 split once, reused by W_res and W2 GEMMs (Kp=768)
    k_splitA<<<4096, 256>>>(p_h1, p_Ab, NN, F1);
    k_splitB<<<1024, 256>>>(W_res, p_Bb, F1, F3);
    gemm_bf16s<<<dim3(F3 / 128, rowTiles), 256>>>(p_Ab, p_Bb, p_res, b_res, NN, F3, 768);
    k_splitB<<<512, 256>>>(W2, p_Bb, F1, F2);
    gemm_bf16s<<<dim3(F2 / 128, rowTiles), 256>>>(p_Ab, p_Bb, p_t, nullptr, NN, F2, 768);
    k_gcn_gather_f2<<<NN, 256>>>(p_t, b2, g1, be1, m1, v1);

    // GCN2: t = a1 @ W3 (Kp=1536); gather+BN2+relu+res+pool
    k_splitA<<<4096, 256>>>(p_a1, p_Ab, NN, F2);
    k_splitB<<<2048, 256>>>(W3, p_Bb, F2, F3);
    gemm_bf16s<<<dim3(F3 / 128, rowTiles), 256>>>(p_Ab, p_Bb, p_t, nullptr, NN, F3, 1536);
    k_gcn_gather_f3<<<NN, 256>>>(p_t, b3, g2, be2, m2, v2, batch);

    // MLP head
    k_head<<<GGG, 256>>>(Wf1, bf1, Wf2, bf2, out);
}